// round 2
// baseline (speedup 1.0000x reference)
#include <cuda_runtime.h>
#include <cstddef>

#define N_NODES 50000
#define N_EDGES 800000
#define NUM_GRAPHS 256
#define IN_DIM 128
#define HDIM 64
#define HID 256
#define EPS_BN 1e-5f
#define SCAN_BLOCKS ((N_NODES + 1023) / 1024)

// ---------------- device scratch (no allocation allowed) ----------------
__device__ __align__(256) int   g_deg[N_NODES];
__device__ __align__(256) int   g_row_start[N_NODES + 1];
__device__ __align__(256) int   g_cursor[N_NODES];
__device__ __align__(256) int   g_csr[N_EDGES];
__device__ __align__(256) int   g_blocksum[64];
__device__ __align__(256) int   g_gstart[NUM_GRAPHS + 1];
__device__ __align__(256) float g_agg[N_NODES * IN_DIM];
__device__ __align__(256) float g_hA[N_NODES * HDIM];
__device__ __align__(256) float g_hB[N_NODES * HDIM];
__device__ __align__(256) float g_pooled[NUM_GRAPHS * HDIM];
__device__ __align__(256) float g_c1[NUM_GRAPHS * HID];
__device__ __align__(256) float g_c2[NUM_GRAPHS * (HID / 2)];
__device__ __align__(256) float g_c3[NUM_GRAPHS * (HID / 4)];
__device__ int g_ei64;   // 1 if edge_index is int64, 0 if int32
__device__ int g_b64;    // same for batch

// ---------------- dtype detection (int64 vs int32), all probes in-bounds ----
__global__ void detect_kernel(const void* ei, const void* batch) {
    if (threadIdx.x == 0 && blockIdx.x == 0) {
        // edge_index: probe first 64 int64-candidate high words (indices < 130,
        // in-bounds for either dtype since 2*N_EDGES ints exist even as int32)
        const int* p = (const int*)ei;
        int is64 = 1;
        for (int i = 0; i < 64; i++) {
            if (p[2 * i + 1] != 0) { is64 = 0; break; }
        }
        g_ei64 = is64;
        // batch: probe around the midpoint. As int64 candidates i in
        // [12500,12564): reads int32 slots up to 2*12563+1 = 25127 < 50000 -> safe
        // either way. Sorted batch values there are ~64-128, i.e. nonzero.
        const int* pb = (const int*)batch;
        int b64 = 1;
        for (int i = 12500; i < 12564; i++) {
            if (pb[2 * i + 1] != 0) { b64 = 0; break; }
        }
        g_b64 = b64;
    }
}

__device__ __forceinline__ int idx_at(const void* p, long long i, int is64) {
    return is64 ? (int)((const long long*)p)[i] : ((const int*)p)[i];
}

// ---------------- CSR build ----------------
__global__ void zero_kernel() {
    int t = blockIdx.x * blockDim.x + threadIdx.x;
    if (t < N_NODES) { g_deg[t] = 0; g_cursor[t] = 0; }
}

__global__ void count_deg_kernel(const void* ei) {
    int e = blockIdx.x * blockDim.x + threadIdx.x;
    if (e >= N_EDGES) return;
    int is64 = g_ei64;
    int dst = idx_at(ei, (long long)N_EDGES + e, is64);
    atomicAdd(&g_deg[dst], 1);
}

// --- parallel scan: phase A (per-block inclusive scan) ---
__global__ void scanA_kernel() {
    __shared__ int s[1024];
    int tid = threadIdx.x;
    int idx = blockIdx.x * 1024 + tid;
    int v = (idx < N_NODES) ? g_deg[idx] : 0;
    s[tid] = v;
    __syncthreads();
#pragma unroll
    for (int off = 1; off < 1024; off <<= 1) {
        int t = (tid >= off) ? s[tid - off] : 0;
        __syncthreads();
        s[tid] += t;
        __syncthreads();
    }
    if (idx < N_NODES) g_row_start[idx + 1] = s[tid];
    if (tid == 1023) g_blocksum[blockIdx.x] = s[1023];
}

// --- phase B: scan the 49 block sums (1 block) ---
__global__ void scanB_kernel() {
    __shared__ int s[64];
    int tid = threadIdx.x;   // 64 threads
    int v = (tid < SCAN_BLOCKS) ? g_blocksum[tid] : 0;
    s[tid] = v;
    __syncthreads();
#pragma unroll
    for (int off = 1; off < 64; off <<= 1) {
        int t = (tid >= off) ? s[tid - off] : 0;
        __syncthreads();
        s[tid] += t;
        __syncthreads();
    }
    // exclusive offsets
    if (tid < SCAN_BLOCKS) g_blocksum[tid] = (tid > 0) ? s[tid - 1] : 0;
}

// --- phase C: add block offsets ---
__global__ void scanC_kernel() {
    int idx = blockIdx.x * blockDim.x + threadIdx.x;
    if (idx < N_NODES) g_row_start[idx + 1] += g_blocksum[idx >> 10];
    if (idx == 0) g_row_start[0] = 0;
}

__global__ void fill_csr_kernel(const void* ei) {
    int e = blockIdx.x * blockDim.x + threadIdx.x;
    if (e >= N_EDGES) return;
    int is64 = g_ei64;
    int src = idx_at(ei, e, is64);
    int dst = idx_at(ei, (long long)N_EDGES + e, is64);
    int pos = atomicAdd(&g_cursor[dst], 1);
    g_csr[g_row_start[dst] + pos] = src;
}

// ---------------- pull-style mean aggregation (no float atomics) ------
// CH = number of float4 chunks per feature row. A warp covers consecutive
// chunks of the same node -> each CSR gather is a coalesced 512B (CH=32)
// or 256B (CH=16) read of the source row.
template <int CH>
__global__ void aggregate_kernel(const float* __restrict__ in) {
    int t = blockIdx.x * blockDim.x + threadIdx.x;
    if (t >= N_NODES * CH) return;
    int node = t / CH;
    int c = t % CH;
    int s = g_row_start[node];
    int e = g_row_start[node + 1];
    const float4* in4 = (const float4*)in;
    float4 acc = make_float4(0.f, 0.f, 0.f, 0.f);
    for (int i = s; i < e; i++) {
        int sr = __ldg(&g_csr[i]);
        float4 v = __ldg(&in4[(size_t)sr * CH + c]);
        acc.x += v.x; acc.y += v.y; acc.z += v.z; acc.w += v.w;
    }
    float inv = 1.0f / fmaxf((float)(e - s), 1.0f);
    acc.x *= inv; acc.y *= inv; acc.z *= inv; acc.w *= inv;
    ((float4*)g_agg)[t] = acc;
}

// ---------------- SAGE linear: out = agg@Wl + bl + x@Wr  (64 outputs) --
// block: 256 threads; tile: 64 nodes x 64 cols; thread tile 4x4; K chunked by 32
template <int K>
__global__ __launch_bounds__(256)
void sage_gemm_kernel(const float* __restrict__ agg, const float* __restrict__ xin,
                      const float* __restrict__ Wl, const float* __restrict__ bl,
                      const float* __restrict__ Wr, float* __restrict__ out) {
    __shared__ float As[64 * 36];   // stride 36 to dodge bank conflicts
    __shared__ float Xs[64 * 36];
    __shared__ float Wls[32 * 64];
    __shared__ float Wrs[32 * 64];

    int nb = blockIdx.x * 64;
    int tid = threadIdx.x;
    int tr = tid >> 4;       // 0..15 -> node group (4 nodes)
    int tc = tid & 15;       // 0..15 -> col group (4 cols)

    float acc[4][4];
#pragma unroll
    for (int i = 0; i < 4; i++)
#pragma unroll
        for (int j = 0; j < 4; j++) acc[i][j] = 0.0f;

    for (int k0 = 0; k0 < K; k0 += 32) {
        // load features: 64 nodes x 32 k = 512 float4
        for (int q = tid; q < 512; q += 256) {
            int n = q >> 3;
            int kq = q & 7;
            int gn = nb + n;
            float4 va = make_float4(0.f, 0.f, 0.f, 0.f);
            float4 vx = va;
            if (gn < N_NODES) {
                va = *(const float4*)&agg[(size_t)gn * K + k0 + kq * 4];
                vx = *(const float4*)&xin[(size_t)gn * K + k0 + kq * 4];
            }
            *(float4*)&As[n * 36 + kq * 4] = va;
            *(float4*)&Xs[n * 36 + kq * 4] = vx;
        }
        // load weights: 32 k x 64 cols = 512 float4
        for (int q = tid; q < 512; q += 256) {
            int k = q >> 4;
            int j4 = q & 15;
            *(float4*)&Wls[k * 64 + j4 * 4] = *(const float4*)&Wl[(size_t)(k0 + k) * 64 + j4 * 4];
            *(float4*)&Wrs[k * 64 + j4 * 4] = *(const float4*)&Wr[(size_t)(k0 + k) * 64 + j4 * 4];
        }
        __syncthreads();

#pragma unroll
        for (int kk = 0; kk < 32; kk++) {
            float4 wl = *(const float4*)&Wls[kk * 64 + tc * 4];
            float4 wr = *(const float4*)&Wrs[kk * 64 + tc * 4];
#pragma unroll
            for (int i = 0; i < 4; i++) {
                float a = As[(tr * 4 + i) * 36 + kk];
                float x = Xs[(tr * 4 + i) * 36 + kk];
                acc[i][0] += a * wl.x + x * wr.x;
                acc[i][1] += a * wl.y + x * wr.y;
                acc[i][2] += a * wl.z + x * wr.z;
                acc[i][3] += a * wl.w + x * wr.w;
            }
        }
        __syncthreads();
    }

    float4 blv = *(const float4*)&bl[tc * 4];
#pragma unroll
    for (int i = 0; i < 4; i++) {
        int gn = nb + tr * 4 + i;
        if (gn < N_NODES) {
            float4 o;
            o.x = acc[i][0] + blv.x;
            o.y = acc[i][1] + blv.y;
            o.z = acc[i][2] + blv.z;
            o.w = acc[i][3] + blv.w;
            *(float4*)&out[(size_t)gn * 64 + tc * 4] = o;
        }
    }
}

// ---------------- global mean pool (batch is sorted -> contiguous ranges) --
// one thread per graph boundary: binary search first index with batch[i] >= g
__global__ void graph_bounds_kernel(const void* __restrict__ batch) {
    int g = blockIdx.x * blockDim.x + threadIdx.x;
    if (g > NUM_GRAPHS) return;
    int b64 = g_b64;
    int lo = 0, hi = N_NODES;
    while (lo < hi) {
        int mid = (lo + hi) >> 1;
        if (idx_at(batch, mid, b64) < g) lo = mid + 1; else hi = mid;
    }
    g_gstart[g] = lo;
}

// one block per graph, 64 threads (one per feature), coalesced reduction
__global__ void pool_kernel(const float* __restrict__ h) {
    int g = blockIdx.x;
    int f = threadIdx.x;
    int s = g_gstart[g];
    int e = g_gstart[g + 1];
    float acc = 0.0f;
    for (int i = s; i < e; i++)
        acc += h[(size_t)i * HDIM + f];
    g_pooled[g * HDIM + f] = acc / fmaxf((float)(e - s), 1.0f);
}

// ---------------- MLP head ----------------
__global__ void lin_kernel(const float* __restrict__ in, const float* __restrict__ W,
                           const float* __restrict__ b, float* __restrict__ out,
                           int Kdim, int Jdim) {
    int t = blockIdx.x * blockDim.x + threadIdx.x;
    if (t >= NUM_GRAPHS * Jdim) return;
    int g = t / Jdim;
    int j = t % Jdim;
    float acc = b[j];
    for (int k = 0; k < Kdim; k++)
        acc += __ldg(&in[g * Kdim + k]) * __ldg(&W[k * Jdim + j]);
    out[t] = acc;
}

__device__ __forceinline__ float blkred256(float v) {
    __shared__ float sh[256];
    int tid = threadIdx.x;
    sh[tid] = v;
    __syncthreads();
    for (int o = 128; o > 0; o >>= 1) {
        if (tid < o) sh[tid] += sh[tid + o];
        __syncthreads();
    }
    float r = sh[0];
    __syncthreads();
    return r;
}

// one block per column, 256 threads = 256 graph rows; training-mode BN + tanh, in-place
__global__ void bn_tanh_kernel(float* __restrict__ c, const float* __restrict__ gamma,
                               const float* __restrict__ beta, int Jdim) {
    int col = blockIdx.x;
    int r = threadIdx.x;
    float v = c[r * Jdim + col];
    float s = blkred256(v);
    __shared__ float mean_s;
    if (r == 0) mean_s = s * (1.0f / NUM_GRAPHS);
    __syncthreads();
    float d = v - mean_s;
    float s2 = blkred256(d * d);
    __shared__ float inv_s;
    if (r == 0) inv_s = rsqrtf(s2 * (1.0f / NUM_GRAPHS) + EPS_BN);
    __syncthreads();
    c[r * Jdim + col] = tanhf(d * inv_s * gamma[col] + beta[col]);
}

// ---------------- launcher ----------------
extern "C" void kernel_launch(void* const* d_in, const int* in_sizes, int n_in,
                              void* d_out, int out_size) {
    const float* x       = (const float*)d_in[0];
    const void*  ei      = d_in[1];
    const void*  batch   = d_in[2];
    const float* W1l     = (const float*)d_in[3];
    const float* b1l     = (const float*)d_in[4];
    const float* W1r     = (const float*)d_in[5];
    const float* W2l     = (const float*)d_in[6];
    const float* b2l     = (const float*)d_in[7];
    const float* W2r     = (const float*)d_in[8];
    const float* W3l     = (const float*)d_in[9];
    const float* b3l     = (const float*)d_in[10];
    const float* W3r     = (const float*)d_in[11];
    const float* lin1_w  = (const float*)d_in[12];
    const float* lin1_b  = (const float*)d_in[13];
    const float* g1      = (const float*)d_in[14];
    const float* be1     = (const float*)d_in[15];
    const float* lin2_w  = (const float*)d_in[16];
    const float* lin2_b  = (const float*)d_in[17];
    const float* g2      = (const float*)d_in[18];
    const float* be2     = (const float*)d_in[19];
    const float* lin3_w  = (const float*)d_in[20];
    const float* lin3_b  = (const float*)d_in[21];
    const float* g3      = (const float*)d_in[22];
    const float* be3     = (const float*)d_in[23];
    const float* lin4_w  = (const float*)d_in[24];
    const float* lin4_b  = (const float*)d_in[25];
    float* out = (float*)d_out;

    float *agg, *hA, *hB, *pooled, *c1, *c2, *c3;
    cudaGetSymbolAddress((void**)&agg,    g_agg);
    cudaGetSymbolAddress((void**)&hA,     g_hA);
    cudaGetSymbolAddress((void**)&hB,     g_hB);
    cudaGetSymbolAddress((void**)&pooled, g_pooled);
    cudaGetSymbolAddress((void**)&c1,     g_c1);
    cudaGetSymbolAddress((void**)&c2,     g_c2);
    cudaGetSymbolAddress((void**)&c3,     g_c3);

    detect_kernel<<<1, 32>>>(ei, batch);
    zero_kernel<<<(N_NODES + 255) / 256, 256>>>();
    count_deg_kernel<<<(N_EDGES + 255) / 256, 256>>>(ei);
    scanA_kernel<<<SCAN_BLOCKS, 1024>>>();
    scanB_kernel<<<1, 64>>>();
    scanC_kernel<<<(N_NODES + 255) / 256, 256>>>();
    fill_csr_kernel<<<(N_EDGES + 255) / 256, 256>>>(ei);

    // layer 1: IN=128
    aggregate_kernel<IN_DIM / 4><<<(N_NODES * (IN_DIM / 4) + 255) / 256, 256>>>(x);
    sage_gemm_kernel<IN_DIM><<<(N_NODES + 63) / 64, 256>>>(agg, x, W1l, b1l, W1r, hA);

    // layer 2: 64 -> 64
    aggregate_kernel<HDIM / 4><<<(N_NODES * (HDIM / 4) + 255) / 256, 256>>>(hA);
    sage_gemm_kernel<HDIM><<<(N_NODES + 63) / 64, 256>>>(agg, hA, W2l, b2l, W2r, hB);

    // layer 3: 64 -> 64
    aggregate_kernel<HDIM / 4><<<(N_NODES * (HDIM / 4) + 255) / 256, 256>>>(hB);
    sage_gemm_kernel<HDIM><<<(N_NODES + 63) / 64, 256>>>(agg, hB, W3l, b3l, W3r, hA);

    // global mean pool (sorted batch -> contiguous per-graph ranges, no atomics)
    graph_bounds_kernel<<<2, 256>>>(batch);
    pool_kernel<<<NUM_GRAPHS, HDIM>>>(hA);

    // MLP head with training-mode BN + tanh
    lin_kernel<<<(NUM_GRAPHS * HID + 255) / 256, 256>>>(pooled, lin1_w, lin1_b, c1, HDIM, HID);
    bn_tanh_kernel<<<HID, 256>>>(c1, g1, be1, HID);
    lin_kernel<<<(NUM_GRAPHS * (HID / 2) + 255) / 256, 256>>>(c1, lin2_w, lin2_b, c2, HID, HID / 2);
    bn_tanh_kernel<<<HID / 2, 256>>>(c2, g2, be2, HID / 2);
    lin_kernel<<<(NUM_GRAPHS * (HID / 4) + 255) / 256, 256>>>(c2, lin3_w, lin3_b, c3, HID / 2, HID / 4);
    bn_tanh_kernel<<<HID / 4, 256>>>(c3, g3, be3, HID / 4);
    lin_kernel<<<(NUM_GRAPHS * 10 + 255) / 256, 256>>>(c3, lin4_w, lin4_b, out, HID / 4, 10);
}